// round 10
// baseline (speedup 1.0000x reference)
#include <cuda_runtime.h>
#include <math.h>

// Problem constants (fixed by the dataset)
#define D      300
#define D4     75      // D / 4 (float4 slabs; 1200B rows are 16B-aligned)
#define NCTX   10
#define NNEG   20
#define NROWS  21      // 1 positive + 20 negatives
#define THREADS 256
#define NWARPS  (THREADS / 32)

__device__ __forceinline__ float log_sigmoid(float x) {
    // numerically stable: min(x,0) - log1p(exp(-|x|))
    return fminf(x, 0.0f) - log1pf(__expf(-fabsf(x)));
}

__global__ void zero_out_kernel(float* out) { out[0] = 0.0f; }

__global__ __launch_bounds__(THREADS)
void cbow_loss_kernel(const int* __restrict__ ctx_words,   // [B, NCTX]
                      const int* __restrict__ center_word, // [B]
                      const int* __restrict__ neg_words,   // [B, NNEG]
                      const float* __restrict__ in_w,      // [V, D]
                      const float* __restrict__ out_w,     // [V, D]
                      float* __restrict__ out,             // [1]
                      float neg_inv_B)                     // -1.0f / B
{
    const int b   = blockIdx.x;
    const int tid = threadIdx.x;
    const int warp = tid >> 5;
    const int lane = tid & 31;

    __shared__ __align__(16) float s_ctx[D];   // mean-pooled context embedding
    __shared__ float s_warp[NWARPS];
    __shared__ int   s_cidx[NCTX];             // context row indices
    __shared__ int   s_tidx[NROWS];            // target row indices (pos + negs)

    // ---- stage indices once per CTA ----
    if (tid < NCTX) s_cidx[tid] = ctx_words[b * NCTX + tid];
    if (tid >= 32 && tid < 32 + NROWS) {
        int r = tid - 32;
        s_tidx[r] = (r == 0) ? center_word[b] : neg_words[b * NNEG + (r - 1)];
    }
    __syncthreads();

    // ---- Phase 1: ctx mean (float4 slabs, 75 active threads, MLP=10) ----
    if (tid < D4) {
        float4 acc = make_float4(0.f, 0.f, 0.f, 0.f);
        #pragma unroll
        for (int c = 0; c < NCTX; c++) {
            const float4* row = reinterpret_cast<const float4*>(
                in_w + (size_t)s_cidx[c] * D);
            float4 v = __ldg(&row[tid]);
            acc.x += v.x; acc.y += v.y; acc.z += v.z; acc.w += v.w;
        }
        const float inv = 1.0f / (float)NCTX;
        float4* cm = reinterpret_cast<float4*>(s_ctx);
        cm[tid] = make_float4(acc.x * inv, acc.y * inv, acc.z * inv, acc.w * inv);
    }
    __syncthreads();

    // ---- Phase 2: 21 dot products, warps round-robin over target rows ----
    const float4* cm = reinterpret_cast<const float4*>(s_ctx);
    float wsum = 0.0f;
    for (int r = warp; r < NROWS; r += NWARPS) {
        const float4* row = reinterpret_cast<const float4*>(
            out_w + (size_t)s_tidx[r] * D);
        float p = 0.0f;
        #pragma unroll
        for (int j = lane; j < D4; j += 32) {
            float4 a = __ldg(&row[j]);
            float4 c = cm[j];
            p = fmaf(a.x, c.x, p);
            p = fmaf(a.y, c.y, p);
            p = fmaf(a.z, c.z, p);
            p = fmaf(a.w, c.w, p);
        }
        #pragma unroll
        for (int o = 16; o > 0; o >>= 1)
            p += __shfl_xor_sync(0xffffffffu, p, o);
        if (lane == 0) {
            float score = (r == 0) ? p : -p;   // negatives use log_sigmoid(-score)
            wsum += log_sigmoid(score);
        }
    }
    if (lane == 0) s_warp[warp] = wsum;
    __syncthreads();

    // ---- block reduce + one global atomic per CTA ----
    if (tid == 0) {
        float s = 0.0f;
        #pragma unroll
        for (int w = 0; w < NWARPS; w++) s += s_warp[w];
        atomicAdd(out, s * neg_inv_B);   // loss = -(1/B) * sum_b s_b
    }
}

extern "C" void kernel_launch(void* const* d_in, const int* in_sizes, int n_in,
                              void* d_out, int out_size) {
    const int*   ctx_words   = (const int*)d_in[0];   // [B, NCTX]
    const int*   center_word = (const int*)d_in[1];   // [B]
    const int*   neg_words   = (const int*)d_in[2];   // [B, NNEG]
    const float* in_w        = (const float*)d_in[3]; // [V, D]
    const float* out_w       = (const float*)d_in[4]; // [V, D]
    float*       out         = (float*)d_out;

    const int B = in_sizes[1];

    zero_out_kernel<<<1, 1>>>(out);
    cbow_loss_kernel<<<B, THREADS>>>(ctx_words, center_word, neg_words,
                                     in_w, out_w, out, -1.0f / (float)B);
}

// round 11
// speedup vs baseline: 1.0259x; 1.0259x over previous
#include <cuda_runtime.h>
#include <math.h>

// Problem constants (fixed by the dataset)
#define D      300
#define D4     75      // D / 4 (float4 slabs; 1200B rows are 16B-aligned)
#define NCTX   10
#define NNEG   20
#define NROWS  21      // 1 positive + 20 negatives
#define THREADS 256
#define NWARPS  (THREADS / 32)

__device__ __forceinline__ float log_sigmoid(float x) {
    // numerically stable: min(x,0) - log1p(exp(-|x|))
    return fminf(x, 0.0f) - log1pf(__expf(-fabsf(x)));
}

__global__ void zero_out_kernel(float* out) { out[0] = 0.0f; }

__global__ __launch_bounds__(THREADS)
void cbow_loss_kernel(const int* __restrict__ ctx_words,   // [B, NCTX]
                      const int* __restrict__ center_word, // [B]
                      const int* __restrict__ neg_words,   // [B, NNEG]
                      const float* __restrict__ in_w,      // [V, D]
                      const float* __restrict__ out_w,     // [V, D]
                      float* __restrict__ out,             // [1]
                      float neg_inv_B)                     // -1.0f / B
{
    const int b   = blockIdx.x;
    const int tid = threadIdx.x;
    const int warp = tid >> 5;
    const int lane = tid & 31;

    __shared__ __align__(16) float s_ctx[D];   // mean-pooled context embedding
    __shared__ float s_warp[NWARPS];
    __shared__ int   s_cidx[NCTX];             // context row indices
    __shared__ int   s_tidx[NROWS];            // target row indices (pos + negs)

    // ---- stage indices once per CTA ----
    if (tid < NCTX) s_cidx[tid] = ctx_words[b * NCTX + tid];
    if (tid >= 32 && tid < 32 + NROWS) {
        int r = tid - 32;
        s_tidx[r] = (r == 0) ? center_word[b] : neg_words[b * NNEG + (r - 1)];
    }
    __syncthreads();

    // ---- Phase 1: ctx mean (float4 slabs, 75 active threads, MLP=10) ----
    if (tid < D4) {
        float4 acc = make_float4(0.f, 0.f, 0.f, 0.f);
        #pragma unroll
        for (int c = 0; c < NCTX; c++) {
            const float4* row = reinterpret_cast<const float4*>(
                in_w + (size_t)s_cidx[c] * D);
            float4 v = __ldg(&row[tid]);
            acc.x += v.x; acc.y += v.y; acc.z += v.z; acc.w += v.w;
        }
        const float inv = 1.0f / (float)NCTX;
        float4* cm = reinterpret_cast<float4*>(s_ctx);
        cm[tid] = make_float4(acc.x * inv, acc.y * inv, acc.z * inv, acc.w * inv);
    }
    __syncthreads();

    // ---- Phase 2: 21 dot products, warps round-robin over target rows ----
    const float4* cm = reinterpret_cast<const float4*>(s_ctx);
    float wsum = 0.0f;
    for (int r = warp; r < NROWS; r += NWARPS) {
        const float4* row = reinterpret_cast<const float4*>(
            out_w + (size_t)s_tidx[r] * D);
        float p = 0.0f;
        #pragma unroll
        for (int j = lane; j < D4; j += 32) {
            float4 a = __ldg(&row[j]);
            float4 c = cm[j];
            p = fmaf(a.x, c.x, p);
            p = fmaf(a.y, c.y, p);
            p = fmaf(a.z, c.z, p);
            p = fmaf(a.w, c.w, p);
        }
        #pragma unroll
        for (int o = 16; o > 0; o >>= 1)
            p += __shfl_xor_sync(0xffffffffu, p, o);
        if (lane == 0) {
            float score = (r == 0) ? p : -p;   // negatives use log_sigmoid(-score)
            wsum += log_sigmoid(score);
        }
    }
    if (lane == 0) s_warp[warp] = wsum;
    __syncthreads();

    // ---- block reduce + one global atomic per CTA ----
    if (tid == 0) {
        float s = 0.0f;
        #pragma unroll
        for (int w = 0; w < NWARPS; w++) s += s_warp[w];
        atomicAdd(out, s * neg_inv_B);   // loss = -(1/B) * sum_b s_b
    }
}

extern "C" void kernel_launch(void* const* d_in, const int* in_sizes, int n_in,
                              void* d_out, int out_size) {
    const int*   ctx_words   = (const int*)d_in[0];   // [B, NCTX]
    const int*   center_word = (const int*)d_in[1];   // [B]
    const int*   neg_words   = (const int*)d_in[2];   // [B, NNEG]
    const float* in_w        = (const float*)d_in[3]; // [V, D]
    const float* out_w       = (const float*)d_in[4]; // [V, D]
    float*       out         = (float*)d_out;

    const int B = in_sizes[1];

    zero_out_kernel<<<1, 1>>>(out);
    cbow_loss_kernel<<<B, THREADS>>>(ctx_words, center_word, neg_words,
                                     in_w, out_w, out, -1.0f / (float)B);
}